// round 1
// baseline (speedup 1.0000x reference)
#include <cuda_runtime.h>
#include <cuda_bf16.h>

// Problem shape (fixed by the dataset): points (B=4, C=84, H=512, W=512) fp32.
// probs = max over channels [0, 80); 3x3 NMS with raster tie-breaking; out = points * mask.

constexpr int B_  = 4;
constexpr int C_  = 84;
constexpr int CM_ = 80;      // channels participating in the max (C - 4)
constexpr int H_  = 512;
constexpr int W_  = 512;
constexpr int HW_ = H_ * W_;          // 262144
constexpr int HW4_ = HW_ / 4;         // 65536 float4 per (b, channel) plane
constexpr int W4_ = W_ / 4;           // 128

// Scratch: per-pixel channel-max. 4 MB — fits entirely in L2.
__device__ float g_probs[B_ * HW_];

// ---------------------------------------------------------------------------
// Kernel A: probs[b,h,w] = max_{c<80} points[b,c,h,w]   (float4 vectorized)
// ---------------------------------------------------------------------------
__global__ __launch_bounds__(256)
void probs_kernel(const float* __restrict__ pts) {
    int t = blockIdx.x * blockDim.x + threadIdx.x;   // 0 .. B_*HW4_ (262144)
    int b = t >> 16;              // t / HW4_
    int o = t & (HW4_ - 1);       // float4 index within plane

    const float4* base = reinterpret_cast<const float4*>(pts) + (long)b * C_ * HW4_ + o;

    float4 m = base[0];
    #pragma unroll 8
    for (int c = 1; c < CM_; c++) {
        float4 v = base[(long)c * HW4_];
        m.x = fmaxf(m.x, v.x);
        m.y = fmaxf(m.y, v.y);
        m.z = fmaxf(m.z, v.z);
        m.w = fmaxf(m.w, v.w);
    }
    reinterpret_cast<float4*>(g_probs)[(long)b * HW4_ + o] = m;
}

// ---------------------------------------------------------------------------
// Kernel B: compute 3x3 NMS mask from g_probs (L2-resident), then
//           out[b,c,h,w] = points[b,c,h,w] * mask[b,h,w] for all 84 channels.
// One thread per float4 of pixels (4 consecutive w).
// Tie-breaking (center_idx=4 in 3x3 raster order):
//   neighbors at raster positions BEFORE center ((-1,-1),(-1,0),(-1,+1),(0,-1)): strict  >
//   neighbors AFTER center ((0,+1),(+1,-1),(+1,0),(+1,+1)):                       >=
// OOB neighbors compare against 0.0f (zero padding), per batch.
// ---------------------------------------------------------------------------
__global__ __launch_bounds__(256)
void nms_mul_kernel(const float* __restrict__ pts, float* __restrict__ out) {
    int t = blockIdx.x * blockDim.x + threadIdx.x;   // 0 .. B_*HW4_
    int b = t >> 16;
    int o = t & (HW4_ - 1);
    int h  = o >> 7;              // o / W4_
    int w0 = (o & (W4_ - 1)) * 4; // leftmost pixel column of this float4

    const float* pr = g_probs + (long)b * HW_;

    // Load the 3-row x 6-col probs neighborhood (cols w0-1 .. w0+4), OOB -> 0.
    float r[3][6];
    #pragma unroll
    for (int i = 0; i < 3; i++) {
        int hh = h - 1 + i;
        bool hv = (hh >= 0) & (hh < H_);
        #pragma unroll
        for (int j = 0; j < 6; j++) {
            int ww = w0 - 1 + j;
            bool wv = (ww >= 0) & (ww < W_);
            r[i][j] = (hv & wv) ? __ldg(pr + hh * W_ + ww) : 0.0f;
        }
    }

    // Per-lane masks.
    float m[4];
    #pragma unroll
    for (int j = 0; j < 4; j++) {
        float c = r[1][j + 1];
        bool k = (c >  r[0][j]) & (c >  r[0][j + 1]) & (c >  r[0][j + 2])
               & (c >  r[1][j])
               & (c >= r[1][j + 2])
               & (c >= r[2][j]) & (c >= r[2][j + 1]) & (c >= r[2][j + 2]);
        m[j] = k ? 1.0f : 0.0f;
    }

    // Multiply all 84 channels.
    long base = (long)b * C_ * HW4_ + o;
    const float4* in  = reinterpret_cast<const float4*>(pts) + base;
    float4*       op  = reinterpret_cast<float4*>(out) + base;
    #pragma unroll 4
    for (int c = 0; c < C_; c++) {
        float4 v = in[(long)c * HW4_];
        v.x *= m[0];
        v.y *= m[1];
        v.z *= m[2];
        v.w *= m[3];
        op[(long)c * HW4_] = v;
    }
}

extern "C" void kernel_launch(void* const* d_in, const int* in_sizes, int n_in,
                              void* d_out, int out_size) {
    const float* pts = (const float*)d_in[0];
    float* out = (float*)d_out;

    constexpr int TPB = 256;
    constexpr int NVEC = B_ * HW4_;          // 262144 threads
    constexpr int BLOCKS = NVEC / TPB;       // 1024

    probs_kernel<<<BLOCKS, TPB>>>(pts);
    nms_mul_kernel<<<BLOCKS, TPB>>>(pts, out);
}